// round 14
// baseline (speedup 1.0000x reference)
#include <cuda_runtime.h>
#include <cuda_bf16.h>
#include <math.h>
#include <stdint.h>

#define Bdim 4
#define Sdim 2048
#define Ddim 768
#define Edim 8
#define Hdim 3072
#define NTOK (Bdim * Sdim)        // 8192
#define NDISP (NTOK * 2)          // 16384

// ---------------- scratch ------------------------------------------------------
__device__ int   g_cnt[Edim];
__device__ int   g_off[Edim];
__device__ int   g_cur[Edim];
__device__ int   g_flag;
__device__ int   g_top_e[NDISP];
__device__ float g_top_g[NDISP];
__device__ int   g_tok[NDISP];
__device__ float g_gate[NDISP];
__device__ int   g_pos[NDISP];
__device__ float g_h[(size_t)NDISP * Hdim];       // fp32 h (fallback path)
__device__ float g_yd[(size_t)NDISP * Ddim];
__device__ __nv_bfloat16 g_xhi[(size_t)NTOK * Ddim];
__device__ __nv_bfloat16 g_xlo[(size_t)NTOK * Ddim];
__device__ __nv_bfloat16 g_hhi[(size_t)NDISP * Hdim];
__device__ __nv_bfloat16 g_hlo[(size_t)NDISP * Hdim];
__device__ __nv_bfloat16 g_w1hi[(size_t)Edim * Hdim * Ddim];  // [E][H][D]
__device__ __nv_bfloat16 g_w1lo[(size_t)Edim * Hdim * Ddim];
__device__ __nv_bfloat16 g_w2hi[(size_t)Edim * Ddim * Hdim];  // [E][D][H]
__device__ __nv_bfloat16 g_w2lo[(size_t)Edim * Ddim * Hdim];

// ---------------- helpers ------------------------------------------------------
__device__ __forceinline__ void mma_bf16(float* d, const uint32_t* a,
                                         uint32_t b0, uint32_t b1) {
    asm volatile("mma.sync.aligned.m16n8k16.row.col.f32.bf16.bf16.f32 "
                 "{%0,%1,%2,%3}, {%4,%5,%6,%7}, {%8,%9}, {%0,%1,%2,%3};"
                 : "+f"(d[0]), "+f"(d[1]), "+f"(d[2]), "+f"(d[3])
                 : "r"(a[0]), "r"(a[1]), "r"(a[2]), "r"(a[3]), "r"(b0), "r"(b1));
}
__device__ __forceinline__ unsigned long long pack2(float a) {
    unsigned long long r;
    asm("mov.b64 %0, {%1, %1};" : "=l"(r) : "r"(__float_as_uint(a)));
    return r;
}
__device__ __forceinline__ void fma2(unsigned long long& d, unsigned long long a,
                                     unsigned long long b) {
    asm("fma.rn.f32x2 %0, %1, %2, %0;" : "+l"(d) : "l"(a), "l"(b));
}
__device__ __forceinline__ float2 unpack2(unsigned long long v) {
    uint32_t lo, hi;
    asm("mov.b64 {%0, %1}, %2;" : "=r"(lo), "=r"(hi) : "l"(v));
    float2 f;
    f.x = __uint_as_float(lo);
    f.y = __uint_as_float(hi);
    return f;
}

// ---------------- small kernels --------------------------------------------------
__global__ void zero_kernel() {
    int t = threadIdx.x;
    if (t < Edim) g_cnt[t] = 0;
    if (t == Edim) g_flag = 0;
}

__global__ void router_kernel(const float* __restrict__ x,
                              const float* __restrict__ noise,
                              const float* __restrict__ w_route,
                              const float* __restrict__ b_route,
                              const float* __restrict__ w_noise,
                              const float* __restrict__ b_noise) {
    int warp = (blockIdx.x * blockDim.x + threadIdx.x) >> 5;
    int lane = threadIdx.x & 31;
    if (warp >= NTOK) return;
    const float* xr = x + (size_t)warp * Ddim;
    float ar[Edim], an[Edim];
#pragma unroll
    for (int e = 0; e < Edim; e++) { ar[e] = 0.f; an[e] = 0.f; }
    for (int k = lane; k < Ddim; k += 32) {
        float xv = xr[k];
        const float* wr = w_route + (size_t)k * Edim;
        const float* wn = w_noise + (size_t)k * Edim;
#pragma unroll
        for (int e = 0; e < Edim; e++) { ar[e] += xv * wr[e]; an[e] += xv * wn[e]; }
    }
#pragma unroll
    for (int e = 0; e < Edim; e++) {
#pragma unroll
        for (int o = 16; o > 0; o >>= 1) {
            ar[e] += __shfl_down_sync(0xffffffffu, ar[e], o);
            an[e] += __shfl_down_sync(0xffffffffu, an[e], o);
        }
    }
    if (lane == 0) {
        float nv[Edim];
#pragma unroll
        for (int e = 0; e < Edim; e++) {
            float z = an[e] + b_noise[e];
            float sp = (z > 0.f) ? (z + log1pf(expf(-z))) : log1pf(expf(z));
            nv[e] = ar[e] + b_route[e] + noise[(size_t)warp * Edim + e] * sp;
        }
        int i1 = 0;
#pragma unroll
        for (int e = 1; e < Edim; e++) if (nv[e] > nv[i1]) i1 = e;
        int i2 = -1;
#pragma unroll
        for (int e = 0; e < Edim; e++) {
            if (e == i1) continue;
            if (i2 < 0 || nv[e] > nv[i2]) i2 = e;
        }
        float d = nv[i2] - nv[i1];
        float ex = expf(d);
        float g1 = 1.f / (1.f + ex);
        float g2 = ex / (1.f + ex);
        g_top_e[warp * 2 + 0] = i1;  g_top_g[warp * 2 + 0] = g1;
        g_top_e[warp * 2 + 1] = i2;  g_top_g[warp * 2 + 1] = g2;
        atomicAdd(&g_cnt[i1], 1);
        atomicAdd(&g_cnt[i2], 1);
    }
}

__global__ void scan_kernel() {
    if (threadIdx.x == 0) {
        int acc = 0;
        for (int e = 0; e < Edim; e++) { g_off[e] = acc; g_cur[e] = acc; acc += g_cnt[e]; }
    }
}

__global__ void fill_kernel() {
    int idx = blockIdx.x * blockDim.x + threadIdx.x;
    if (idx >= NDISP) return;
    int t = idx >> 1;
    int e = g_top_e[idx];
    int pos = atomicAdd(&g_cur[e], 1);
    g_tok[pos] = t;
    g_gate[pos] = g_top_g[idx];
    g_pos[idx] = pos;
}

// ---------------- weight transpose + bf16 split ----------------------------------
__global__ void wsplit_kernel(const float* __restrict__ src,
                              __nv_bfloat16* __restrict__ dhi,
                              __nv_bfloat16* __restrict__ dlo,
                              int R, int C) {
    __shared__ float tile[32][33];
    int e = blockIdx.z;
    src += (size_t)e * R * C;
    dhi += (size_t)e * R * C;
    dlo += (size_t)e * R * C;
    int x0 = blockIdx.x * 32, y0 = blockIdx.y * 32;
    int tx = threadIdx.x, ty = threadIdx.y;
#pragma unroll
    for (int j = 0; j < 4; j++)
        tile[ty + j * 8][tx] = src[(size_t)(y0 + ty + j * 8) * C + x0 + tx];
    __syncthreads();
#pragma unroll
    for (int j = 0; j < 4; j++) {
        float v = tile[tx][ty + j * 8];
        __nv_bfloat16 h = __float2bfloat16(v);
        size_t o = (size_t)(x0 + ty + j * 8) * R + y0 + tx;
        dhi[o] = h;
        dlo[o] = __float2bfloat16(v - __bfloat162float(h));
    }
}

__global__ void xsplit_kernel(const float* __restrict__ x) {
    int idx = blockIdx.x * blockDim.x + threadIdx.x;
    if (idx >= NTOK * Ddim) return;
    float v = x[idx];
    __nv_bfloat16 h = __float2bfloat16(v);
    g_xhi[idx] = h;
    g_xlo[idx] = __float2bfloat16(v - __bfloat162float(h));
}

// ---------------- split-bf16 mma.sync GEMM — (256,2), LDG/STS feed ---------------
template <bool FFN1>
__global__ void __launch_bounds__(256, 2)
ffn_t_kernel(const float* __restrict__ bias) {
    constexpr int K    = FFN1 ? Ddim : Hdim;
    constexpr int NOUT = FFN1 ? Hdim : Ddim;
    constexpr int NC   = K / 16;

    int e = blockIdx.z;
    int cnt = g_cnt[e];
    int m0 = blockIdx.y * 128;
    if (m0 >= cnt) return;
    int base = g_off[e];
    int n0 = blockIdx.x * 128;

    // planes: Ah, Al, Bh, Bl — each 128 rows x 16 bf16 (32B rows) = 4KB
    __shared__ __align__(16) uint8_t sT[4 * 4096];
    __shared__ float s_bias[128];

    int tid = threadIdx.x;
    int wid = tid >> 5, lane = tid & 31;
    int g = lane >> 2, t = lane & 3;
    int wm = (wid & 3) * 32;
    int wn = (wid >> 2) * 64;

    if (tid < 128) s_bias[tid] = bias[(size_t)e * NOUT + n0 + tid];

    int row = tid >> 1, half = tid & 1;
    int rr = m0 + row;
    if (rr >= cnt) rr = cnt - 1;   // clamp; epilogue masks
    const __nv_bfloat16 *ah_src, *al_src;
    if (FFN1) {
        int tok = g_tok[base + rr];
        ah_src = g_xhi + (size_t)tok * K + half * 8;
        al_src = g_xlo + (size_t)tok * K + half * 8;
    } else {
        ah_src = g_hhi + (size_t)(base + rr) * K + half * 8;
        al_src = g_hlo + (size_t)(base + rr) * K + half * 8;
    }
    const __nv_bfloat16* bh_src =
        (FFN1 ? g_w1hi : g_w2hi) + ((size_t)e * NOUT + n0 + row) * K + half * 8;
    const __nv_bfloat16* bl_src =
        (FFN1 ? g_w1lo : g_w2lo) + ((size_t)e * NOUT + n0 + row) * K + half * 8;

    uint8_t* dstA = sT + row * 32 + half * 16;

    float4 vAh = *(const float4*)(ah_src);
    float4 vAl = *(const float4*)(al_src);
    float4 vBh = *(const float4*)(bh_src);
    float4 vBl = *(const float4*)(bl_src);

    float acc[2][8][4];
#pragma unroll
    for (int f = 0; f < 2; f++)
#pragma unroll
        for (int gi = 0; gi < 8; gi++)
#pragma unroll
            for (int q = 0; q < 4; q++) acc[f][gi][q] = 0.f;

    for (int c = 0; c < NC; c++) {
        *(float4*)(dstA)         = vAh;
        *(float4*)(dstA + 4096)  = vAl;
        *(float4*)(dstA + 8192)  = vBh;
        *(float4*)(dstA + 12288) = vBl;
        __syncthreads();

        if (c + 1 < NC) {
            vAh = *(const float4*)(ah_src + (c + 1) * 16);
            vAl = *(const float4*)(al_src + (c + 1) * 16);
            vBh = *(const float4*)(bh_src + (c + 1) * 16);
            vBl = *(const float4*)(bl_src + (c + 1) * 16);
        }

        const uint8_t* Ah = sT;
        const uint8_t* Al = sT + 4096;
        const uint8_t* Bh = sT + 8192;
        const uint8_t* Bl = sT + 12288;

        uint32_t ah[2][4], al[2][4];
#pragma unroll
        for (int f = 0; f < 2; f++) {
            int r0 = wm + f * 16 + g;
            ah[f][0] = *(const uint32_t*)(Ah + r0 * 32 + 4 * t);
            ah[f][1] = *(const uint32_t*)(Ah + (r0 + 8) * 32 + 4 * t);
            ah[f][2] = *(const uint32_t*)(Ah + r0 * 32 + 16 + 4 * t);
            ah[f][3] = *(const uint32_t*)(Ah + (r0 + 8) * 32 + 16 + 4 * t);
            al[f][0] = *(const uint32_t*)(Al + r0 * 32 + 4 * t);
            al[f][1] = *(const uint32_t*)(Al + (r0 + 8) * 32 + 4 * t);
            al[f][2] = *(const uint32_t*)(Al + r0 * 32 + 16 + 4 * t);
            al[f][3] = *(const uint32_t*)(Al + (r0 + 8) * 32 + 16 + 4 * t);
        }
#pragma unroll
        for (int gi = 0; gi < 8; gi++) {
            int n = wn + gi * 8 + g;
            uint32_t bh0 = *(const uint32_t*)(Bh + n * 32 + 4 * t);
            uint32_t bh1 = *(const uint32_t*)(Bh + n * 32 + 16 + 4 * t);
            uint32_t bl0 = *(const uint32_t*)(Bl + n * 32 + 4 * t);
            uint32_t bl1 = *(const uint32_t*)(Bl + n * 32 + 16 + 4 * t);
#pragma unroll
            for (int f = 0; f < 2; f++) {
                mma_bf16(acc[f][gi], ah[f], bh0, bh1);
                mma_bf16(acc[f][gi], ah[f], bl0, bl1);
                mma_bf16(acc[f][gi], al[f], bh0, bh1);
            }
        }
        __syncthreads();
    }

    // ---- epilogue ----
#pragma unroll
    for (int f = 0; f < 2; f++) {
#pragma unroll
        for (int dr = 0; dr < 2; dr++) {
            int rowm = m0 + wm + f * 16 + g + dr * 8;
            if (rowm >= cnt) continue;
            float gate = FFN1 ? 1.f : g_gate[base + rowm];
#pragma unroll
            for (int gi = 0; gi < 8; gi++) {
                int cl = wn + gi * 8 + 2 * t;
                float v0 = acc[f][gi][dr * 2 + 0] + s_bias[cl];
                float v1 = acc[f][gi][dr * 2 + 1] + s_bias[cl + 1];
                if (FFN1) {
                    v0 = fmaxf(v0, 0.f);
                    v1 = fmaxf(v1, 0.f);
                    __nv_bfloat16 h0 = __float2bfloat16(v0);
                    __nv_bfloat16 h1 = __float2bfloat16(v1);
                    __nv_bfloat162 ph; ph.x = h0; ph.y = h1;
                    __nv_bfloat162 pl;
                    pl.x = __float2bfloat16(v0 - __bfloat162float(h0));
                    pl.y = __float2bfloat16(v1 - __bfloat162float(h1));
                    size_t o = (size_t)(base + rowm) * NOUT + cl;
                    *(__nv_bfloat162*)(g_hhi + o) = ph;
                    *(__nv_bfloat162*)(g_hlo + o) = pl;
                } else {
                    float2 v;
                    v.x = gate * v0;
                    v.y = gate * v1;
                    *(float2*)(g_yd + (size_t)(base + rowm) * NOUT + cl) = v;
                }
            }
        }
    }
}

// ---------------- sampled self-check ---------------------------------------------
__global__ void check_kernel(const float* __restrict__ x,
                             const float* __restrict__ W1,
                             const float* __restrict__ b1,
                             const float* __restrict__ W2,
                             const float* __restrict__ b2) {
    int blk = blockIdx.x;
    int tid = threadIdx.x;
    int wid = tid >> 5, lane = tid & 31;
    int dr = (blk * 769 + 131) % NDISP;
    int e = 0;
#pragma unroll
    for (int i = 1; i < Edim; i++) if (dr >= g_off[i]) e = i;
    int tok = g_tok[dr];
    float gate = g_gate[dr];

    {
        int hc = (wid * 409 + blk * 131) % Hdim;
        float s = 0.f;
        const float* w = W1 + (size_t)e * Ddim * Hdim + hc;
        const float* xr = x + (size_t)tok * Ddim;
        for (int k = lane; k < Ddim; k += 32) s += xr[k] * w[(size_t)k * Hdim];
#pragma unroll
        for (int o = 16; o > 0; o >>= 1) s += __shfl_down_sync(0xffffffffu, s, o);
        if (lane == 0) {
            float ref = fmaxf(s + b1[(size_t)e * Hdim + hc], 0.f);
            float got = __bfloat162float(g_hhi[(size_t)dr * Hdim + hc]) +
                        __bfloat162float(g_hlo[(size_t)dr * Hdim + hc]);
            if (!(fabsf(got - ref) <= 0.02f + 0.05f * fabsf(ref)))
                atomicOr(&g_flag, 1);
        }
    }
    {
        int dc = (wid * 97 + blk * 29) % Ddim;
        float s = 0.f;
        const float* w = W2 + (size_t)e * Hdim * Ddim + dc;
        for (int k = lane; k < Hdim; k += 32) {
            float hv = __bfloat162float(g_hhi[(size_t)dr * Hdim + k]) +
                       __bfloat162float(g_hlo[(size_t)dr * Hdim + k]);
            s += hv * w[(size_t)k * Ddim];
        }
#pragma unroll
        for (int o = 16; o > 0; o >>= 1) s += __shfl_down_sync(0xffffffffu, s, o);
        if (lane == 0) {
            float ref = gate * (s + b2[(size_t)e * Ddim + dc]);
            float got = g_yd[(size_t)dr * Ddim + dc];
            if (!(fabsf(got - ref) <= 0.02f + 0.05f * fabsf(ref)))
                atomicOr(&g_flag, 2);
        }
    }
}

// ---------------- fallback f32x2 GEMMs (R9-proven, gated on g_flag) --------------
__global__ void __launch_bounds__(256, 2)
ffn1_fb(const float* __restrict__ x, const float* __restrict__ W1,
        const float* __restrict__ b1) {
    if (g_flag == 0) return;
    int e = blockIdx.z;
    int cnt = g_cnt[e];
    int m0 = blockIdx.y * 128;
    if (m0 >= cnt) return;
    int base = g_off[e];
    int n0 = blockIdx.x * 128;
    const float* Bp = W1 + (size_t)e * Ddim * Hdim;

    __shared__ float As[16][132];
    __shared__ float Bs[16][128];
    __shared__ int rows[128];

    int tid = threadIdx.x;
    if (tid < 128) {
        int r = m0 + tid;
        rows[tid] = (r < cnt) ? g_tok[base + r] : -1;
    }
    __syncthreads();

    int arow = tid >> 1, akc = (tid & 1) * 8;
    int bkr = tid >> 4, bnc = (tid & 15) * 8;
    int tm = (tid >> 4) * 8, tn = (tid & 15) * 8;

    unsigned long long acc[8][4];
#pragma unroll
    for (int i = 0; i < 8; i++)
#pragma unroll
        for (int j = 0; j < 4; j++) acc[i][j] = 0ull;

    int trow = rows[arow];
    const float* ap_base = (trow >= 0) ? (x + (size_t)trow * Ddim + akc) : nullptr;
    const float* bp_base = Bp + (size_t)bkr * Hdim + n0 + bnc;

    float4 av0 = make_float4(0.f, 0.f, 0.f, 0.f), av1 = av0;
    if (ap_base) {
        av0 = *(const float4*)(ap_base);
        av1 = *(const float4*)(ap_base + 4);
    }
    float4 bv0 = *(const float4*)(bp_base);
    float4 bv1 = *(const float4*)(bp_base + 4);

    for (int k0 = 0; k0 < Ddim; k0 += 16) {
        __syncthreads();
        As[akc + 0][arow] = av0.x;  As[akc + 1][arow] = av0.y;
        As[akc + 2][arow] = av0.z;  As[akc + 3][arow] = av0.w;
        As[akc + 4][arow] = av1.x;  As[akc + 5][arow] = av1.y;
        As[akc + 6][arow] = av1.z;  As[akc + 7][arow] = av1.w;
        *(float4*)&Bs[bkr][bnc]     = bv0;
        *(float4*)&Bs[bkr][bnc + 4] = bv1;
        __syncthreads();
        if (k0 + 16 < Ddim) {
            if (ap_base) {
                av0 = *(const float4*)(ap_base + k0 + 16);
                av1 = *(const float4*)(ap_base + k0 + 20);
            }
            const float* bp = bp_base + (size_t)(k0 + 16) * Hdim;
            bv0 = *(const float4*)(bp);
            bv1 = *(const float4*)(bp + 4);
        }
#pragma unroll
        for (int kk = 0; kk < 16; kk++) {
            float4 aA = *(const float4*)&As[kk][tm];
            float4 aB = *(const float4*)&As[kk][tm + 4];
            ulonglong2 bA = *(const ulonglong2*)&Bs[kk][tn];
            ulonglong2 bB = *(const ulonglong2*)&Bs[kk][tn + 4];
            unsigned long long b2[4] = {bA.x, bA.y, bB.x, bB.y};
            float a[8] = {aA.x, aA.y, aA.z, aA.w, aB.x, aB.y, aB.z, aB.w};
#pragma unroll
            for (int i = 0; i < 8; i++) {
                unsigned long long ai = pack2(a[i]);
#pragma unroll
                for (int j = 0; j < 4; j++) fma2(acc[i][j], ai, b2[j]);
            }
        }
    }
    const float* b1p = b1 + (size_t)e * Hdim + n0 + tn;
#pragma unroll
    for (int i = 0; i < 8; i++) {
        int r = m0 + tm + i;
        if (r < cnt) {
            float* hp = g_h + (size_t)(base + r) * Hdim + n0 + tn;
#pragma unroll
            for (int j = 0; j < 4; j++) {
                float2 v = unpack2(acc[i][j]);
                float2 o;
                o.x = fmaxf(v.x + b1p[j * 2 + 0], 0.f);
                o.y = fmaxf(v.y + b1p[j * 2 + 1], 0.f);
                *(float2*)(hp + j * 2) = o;
            }
        }
    }
}

__global__ void __launch_bounds__(256, 2)
ffn2_fb(const float* __restrict__ W2, const float* __restrict__ b2) {
    if (g_flag == 0) return;
    int e = blockIdx.z;
    int cnt = g_cnt[e];
    int m0 = blockIdx.y * 128;
    if (m0 >= cnt) return;
    int base = g_off[e];
    int n0 = blockIdx.x * 128;
    const float* Bp = W2 + (size_t)e * Hdim * Ddim;

    __shared__ float As[16][132];
    __shared__ float Bs[16][128];

    int tid = threadIdx.x;
    int arow = tid >> 1, akc = (tid & 1) * 8;
    int bkr = tid >> 4, bnc = (tid & 15) * 8;
    int tm = (tid >> 4) * 8, tn = (tid & 15) * 8;

    int r_a = m0 + arow;
    if (r_a >= cnt) r_a = cnt - 1;
    const float* ap_base = g_h + (size_t)(base + r_a) * Hdim + akc;
    const float* bp_base = Bp + (size_t)bkr * Ddim + n0 + bnc;

    unsigned long long acc[8][4];
#pragma unroll
    for (int i = 0; i < 8; i++)
#pragma unroll
        for (int j = 0; j < 4; j++) acc[i][j] = 0ull;

    float4 av0 = *(const float4*)(ap_base);
    float4 av1 = *(const float4*)(ap_base + 4);
    float4 bv0 = *(const float4*)(bp_base);
    float4 bv1 = *(const float4*)(bp_base + 4);

    for (int k0 = 0; k0 < Hdim; k0 += 16) {
        __syncthreads();
        As[akc + 0][arow] = av0.x;  As[akc + 1][arow] = av0.y;
        As[akc + 2][arow] = av0.z;  As[akc + 3][arow] = av0.w;
        As[akc + 4][arow] = av1.x;  As[akc + 5][arow] = av1.y;
        As[akc + 6][arow] = av1.z;  As[akc + 7][arow] = av1.w;
        *(float4*)&Bs[bkr][bnc]     = bv0;
        *(float4*)&Bs[bkr][bnc + 4] = bv1;
        __syncthreads();
        if (k0 + 16 < Hdim) {
            av0 = *(const float4*)(ap_base + k0 + 16);
            av1 = *(const float4*)(ap_base + k0 + 20);
            const float* bp = bp_base + (size_t)(k0 + 16) * Ddim;
            bv0 = *(const float4*)(bp);
            bv1 = *(const float4*)(bp + 4);
        }
#pragma unroll
        for (int kk = 0; kk < 16; kk++) {
            float4 aA = *(const float4*)&As[kk][tm];
            float4 aB = *(const float4*)&As[kk][tm + 4];
            ulonglong2 bA = *(const ulonglong2*)&Bs[kk][tn];
            ulonglong2 bB = *(const ulonglong2*)&Bs[kk][tn + 4];
            unsigned long long b2v[4] = {bA.x, bA.y, bB.x, bB.y};
            float a[8] = {aA.x, aA.y, aA.z, aA.w, aB.x, aB.y, aB.z, aB.w};
#pragma unroll
            for (int i = 0; i < 8; i++) {
                unsigned long long ai = pack2(a[i]);
#pragma unroll
                for (int j = 0; j < 4; j++) fma2(acc[i][j], ai, b2v[j]);
            }
        }
    }
    const float* b2p = b2 + (size_t)e * Ddim + n0 + tn;
#pragma unroll
    for (int i = 0; i < 8; i++) {
        int r = m0 + tm + i;
        if (r < cnt) {
            float g = g_gate[base + r];
            float* yp = g_yd + (size_t)(base + r) * Ddim + n0 + tn;
#pragma unroll
            for (int j = 0; j < 4; j++) {
                float2 v = unpack2(acc[i][j]);
                float2 o;
                o.x = g * (v.x + b2p[j * 2 + 0]);
                o.y = g * (v.y + b2p[j * 2 + 1]);
                *(float2*)(yp + j * 2) = o;
            }
        }
    }
}

// ---------------- combine ---------------------------------------------------------
__global__ void combine_kernel(float* __restrict__ out) {
    int idx = blockIdx.x * blockDim.x + threadIdx.x;
    int total = NTOK * Ddim / 4;
    if (idx >= total) return;
    int t = idx / (Ddim / 4);
    int d4 = idx % (Ddim / 4);
    int p0 = g_pos[t * 2 + 0];
    int p1 = g_pos[t * 2 + 1];
    float4 a = *(const float4*)(g_yd + (size_t)p0 * Ddim + d4 * 4);
    float4 b = *(const float4*)(g_yd + (size_t)p1 * Ddim + d4 * 4);
    float4 o;
    o.x = a.x + b.x; o.y = a.y + b.y; o.z = a.z + b.z; o.w = a.w + b.w;
    *(float4*)(out + (size_t)t * Ddim + d4 * 4) = o;
}

// ---------------- launch ------------------------------------------------------------
extern "C" void kernel_launch(void* const* d_in, const int* in_sizes, int n_in,
                              void* d_out, int out_size) {
    const float* x       = (const float*)d_in[0];
    const float* noise   = (const float*)d_in[1];
    const float* w_route = (const float*)d_in[2];
    const float* b_route = (const float*)d_in[3];
    const float* w_noise = (const float*)d_in[4];
    const float* b_noise = (const float*)d_in[5];
    const float* W1      = (const float*)d_in[6];
    const float* b1      = (const float*)d_in[7];
    const float* W2      = (const float*)d_in[8];
    const float* b2      = (const float*)d_in[9];
    float* out = (float*)d_out;

    zero_kernel<<<1, 32>>>();
    router_kernel<<<NTOK / 8, 256>>>(x, noise, w_route, b_route, w_noise, b_noise);
    scan_kernel<<<1, 1>>>();
    fill_kernel<<<(NDISP + 255) / 256, 256>>>();
    wsplit_kernel<<<dim3(Hdim / 32, Ddim / 32, Edim), dim3(32, 8)>>>(W1, g_w1hi, g_w1lo, Ddim, Hdim);
    wsplit_kernel<<<dim3(Ddim / 32, Hdim / 32, Edim), dim3(32, 8)>>>(W2, g_w2hi, g_w2lo, Hdim, Ddim);
    xsplit_kernel<<<(NTOK * Ddim + 255) / 256, 256>>>(x);
    // tensor path — (256,2) this time
    ffn_t_kernel<true><<<dim3(Hdim / 128, NDISP / 128, Edim), 256>>>(b1);
    ffn_t_kernel<false><<<dim3(Ddim / 128, NDISP / 128, Edim), 256>>>(b2);
    // self-check; sets g_flag on mismatch
    check_kernel<<<64, 256>>>(x, W1, b1, W2, b2);
    // fallback (no-ops when g_flag == 0)
    ffn1_fb<<<dim3(Hdim / 128, NDISP / 128, Edim), 256>>>(x, W1, b1);
    ffn2_fb<<<dim3(Ddim / 128, NDISP / 128, Edim), 256>>>(W2, b2);
    combine_kernel<<<(NTOK * Ddim / 4 + 255) / 256, 256>>>(out);
}

// round 15
// speedup vs baseline: 2.2156x; 2.2156x over previous
#include <cuda_runtime.h>
#include <math.h>
#include <stdint.h>

#define Bdim 4
#define Sdim 2048
#define Ddim 768
#define Edim 8
#define Hdim 3072
#define NTOK (Bdim * Sdim)        // 8192
#define NDISP (NTOK * 2)          // 16384
#define MAXTILES 144
#define KSPLIT 5

// ---------------- scratch ------------------------------------------------------
__device__ int   g_cnt[Edim];
__device__ int   g_off[Edim];
__device__ int   g_cur[Edim];
__device__ int   g_ntiles;
__device__ int   g_tile_e[MAXTILES];
__device__ int   g_tile_m[MAXTILES];
__device__ int   g_top_e[NDISP];
__device__ float g_top_g[NDISP];
__device__ int   g_tok[NDISP];
__device__ float g_gate[NDISP];
__device__ int   g_pos[NDISP];
__device__ float g_h[(size_t)NDISP * Hdim];   // 201 MB intermediate activations
__device__ float g_yd[(size_t)NDISP * Ddim];  // 50 MB (atomic accumulation target)

// ---------------- f32x2 helpers -------------------------------------------------
__device__ __forceinline__ unsigned long long pack2(float a) {
    unsigned long long r;
    asm("mov.b64 %0, {%1, %1};" : "=l"(r) : "r"(__float_as_uint(a)));
    return r;
}
__device__ __forceinline__ void fma2(unsigned long long& d, unsigned long long a,
                                     unsigned long long b) {
    asm("fma.rn.f32x2 %0, %1, %2, %0;" : "+l"(d) : "l"(a), "l"(b));
}
__device__ __forceinline__ float2 unpack2(unsigned long long v) {
    uint32_t lo, hi;
    asm("mov.b64 {%0, %1}, %2;" : "=r"(lo), "=r"(hi) : "l"(v));
    float2 f;
    f.x = __uint_as_float(lo);
    f.y = __uint_as_float(hi);
    return f;
}

// ---------------- kernel 0: zero counters ----------------------------------------
__global__ void zero_kernel() {
    int t = threadIdx.x;
    if (t < Edim) g_cnt[t] = 0;
}

// ---------------- kernel 0b: zero yd ----------------------------------------------
__global__ void yzero_kernel() {
    size_t idx = (size_t)blockIdx.x * blockDim.x + threadIdx.x;
    size_t total = (size_t)NDISP * Ddim / 4;
    if (idx >= total) return;
    *(float4*)(g_yd + idx * 4) = make_float4(0.f, 0.f, 0.f, 0.f);
}

// ---------------- kernel 1: router (1 warp per token) ---------------------------
__global__ void router_kernel(const float* __restrict__ x,
                              const float* __restrict__ noise,
                              const float* __restrict__ w_route,
                              const float* __restrict__ b_route,
                              const float* __restrict__ w_noise,
                              const float* __restrict__ b_noise) {
    int warp = (blockIdx.x * blockDim.x + threadIdx.x) >> 5;
    int lane = threadIdx.x & 31;
    if (warp >= NTOK) return;
    const float* xr = x + (size_t)warp * Ddim;
    float ar[Edim], an[Edim];
#pragma unroll
    for (int e = 0; e < Edim; e++) { ar[e] = 0.f; an[e] = 0.f; }
    for (int k = lane; k < Ddim; k += 32) {
        float xv = xr[k];
        const float* wr = w_route + (size_t)k * Edim;
        const float* wn = w_noise + (size_t)k * Edim;
#pragma unroll
        for (int e = 0; e < Edim; e++) { ar[e] += xv * wr[e]; an[e] += xv * wn[e]; }
    }
#pragma unroll
    for (int e = 0; e < Edim; e++) {
#pragma unroll
        for (int o = 16; o > 0; o >>= 1) {
            ar[e] += __shfl_down_sync(0xffffffffu, ar[e], o);
            an[e] += __shfl_down_sync(0xffffffffu, an[e], o);
        }
    }
    if (lane == 0) {
        float nv[Edim];
#pragma unroll
        for (int e = 0; e < Edim; e++) {
            float z = an[e] + b_noise[e];
            float sp = (z > 0.f) ? (z + log1pf(expf(-z))) : log1pf(expf(z));
            nv[e] = ar[e] + b_route[e] + noise[(size_t)warp * Edim + e] * sp;
        }
        int i1 = 0;
#pragma unroll
        for (int e = 1; e < Edim; e++) if (nv[e] > nv[i1]) i1 = e;
        int i2 = -1;
#pragma unroll
        for (int e = 0; e < Edim; e++) {
            if (e == i1) continue;
            if (i2 < 0 || nv[e] > nv[i2]) i2 = e;
        }
        float d = nv[i2] - nv[i1];
        float ex = expf(d);
        float g1 = 1.f / (1.f + ex);
        float g2 = ex / (1.f + ex);
        g_top_e[warp * 2 + 0] = i1;  g_top_g[warp * 2 + 0] = g1;
        g_top_e[warp * 2 + 1] = i2;  g_top_g[warp * 2 + 1] = g2;
        atomicAdd(&g_cnt[i1], 1);
        atomicAdd(&g_cnt[i2], 1);
    }
}

// ---------------- kernel 2: prefix scan + compact tile list ---------------------
__global__ void scan_kernel() {
    if (threadIdx.x == 0) {
        int acc = 0;
        for (int e = 0; e < Edim; e++) { g_off[e] = acc; g_cur[e] = acc; acc += g_cnt[e]; }
        int nt = 0;
        for (int e = 0; e < Edim; e++) {
            int tiles = (g_cnt[e] + 127) >> 7;
            for (int t = 0; t < tiles; t++) {
                g_tile_e[nt] = e;
                g_tile_m[nt] = t;
                nt++;
            }
        }
        g_ntiles = nt;
    }
}

// ---------------- kernel 3: fill dispatch lists ----------------------------------
__global__ void fill_kernel() {
    int idx = blockIdx.x * blockDim.x + threadIdx.x;
    if (idx >= NDISP) return;
    int t = idx >> 1;
    int e = g_top_e[idx];
    int pos = atomicAdd(&g_cur[e], 1);
    g_tok[pos] = t;
    g_gate[pos] = g_top_g[idx];
    g_pos[idx] = pos;
}

// ---------------- kernel 4: GEMM1 (R11-proven: 128x128, double-buffered) --------
__global__ void __launch_bounds__(256, 2)
ffn1_kernel(const float* __restrict__ x,
            const float* __restrict__ W1,
            const float* __restrict__ b1) {
    int ty = blockIdx.y;
    if (ty >= g_ntiles) return;
    int e = g_tile_e[ty];
    int cnt = g_cnt[e];
    int m0 = g_tile_m[ty] << 7;
    int base = g_off[e];
    int n0 = blockIdx.x * 128;
    const float* Bp = W1 + (size_t)e * Ddim * Hdim;

    __shared__ float As[2][16][132];
    __shared__ float Bs[2][16][128];
    __shared__ int rows[128];

    int tid = threadIdx.x;
    if (tid < 128) {
        int r = m0 + tid;
        rows[tid] = (r < cnt) ? g_tok[base + r] : -1;
    }
    __syncthreads();

    int arow = tid >> 1, akc = (tid & 1) * 8;
    int bkr = tid >> 4, bnc = (tid & 15) * 8;
    int tm = (tid >> 4) * 8, tn = (tid & 15) * 8;

    unsigned long long acc[8][4];
#pragma unroll
    for (int i = 0; i < 8; i++)
#pragma unroll
        for (int j = 0; j < 4; j++) acc[i][j] = 0ull;

    int trow = rows[arow];
    const float* ap_base = (trow >= 0) ? (x + (size_t)trow * Ddim + akc) : nullptr;
    const float* bp_base = Bp + (size_t)bkr * Hdim + n0 + bnc;

    float4 av0 = make_float4(0.f, 0.f, 0.f, 0.f), av1 = av0;
    if (ap_base) {
        av0 = *(const float4*)(ap_base);
        av1 = *(const float4*)(ap_base + 4);
    }
    float4 bv0 = *(const float4*)(bp_base);
    float4 bv1 = *(const float4*)(bp_base + 4);

    As[0][akc + 0][arow] = av0.x;  As[0][akc + 1][arow] = av0.y;
    As[0][akc + 2][arow] = av0.z;  As[0][akc + 3][arow] = av0.w;
    As[0][akc + 4][arow] = av1.x;  As[0][akc + 5][arow] = av1.y;
    As[0][akc + 6][arow] = av1.z;  As[0][akc + 7][arow] = av1.w;
    *(float4*)&Bs[0][bkr][bnc]     = bv0;
    *(float4*)&Bs[0][bkr][bnc + 4] = bv1;
    __syncthreads();

    constexpr int NC = Ddim / 16;
    for (int c = 0; c < NC; c++) {
        int cur = c & 1, nxt = cur ^ 1;
        if (c + 1 < NC) {
            int k0 = (c + 1) * 16;
            if (ap_base) {
                av0 = *(const float4*)(ap_base + k0);
                av1 = *(const float4*)(ap_base + k0 + 4);
            }
            const float* bp = bp_base + (size_t)k0 * Hdim;
            bv0 = *(const float4*)(bp);
            bv1 = *(const float4*)(bp + 4);
        }
#pragma unroll
        for (int kk = 0; kk < 16; kk++) {
            float4 aA = *(const float4*)&As[cur][kk][tm];
            float4 aB = *(const float4*)&As[cur][kk][tm + 4];
            ulonglong2 bA = *(const ulonglong2*)&Bs[cur][kk][tn];
            ulonglong2 bB = *(const ulonglong2*)&Bs[cur][kk][tn + 4];
            unsigned long long b2[4] = {bA.x, bA.y, bB.x, bB.y};
            float a[8] = {aA.x, aA.y, aA.z, aA.w, aB.x, aB.y, aB.z, aB.w};
#pragma unroll
            for (int i = 0; i < 8; i++) {
                unsigned long long ai = pack2(a[i]);
#pragma unroll
                for (int j = 0; j < 4; j++) fma2(acc[i][j], ai, b2[j]);
            }
        }
        if (c + 1 < NC) {
            As[nxt][akc + 0][arow] = av0.x;  As[nxt][akc + 1][arow] = av0.y;
            As[nxt][akc + 2][arow] = av0.z;  As[nxt][akc + 3][arow] = av0.w;
            As[nxt][akc + 4][arow] = av1.x;  As[nxt][akc + 5][arow] = av1.y;
            As[nxt][akc + 6][arow] = av1.z;  As[nxt][akc + 7][arow] = av1.w;
            *(float4*)&Bs[nxt][bkr][bnc]     = bv0;
            *(float4*)&Bs[nxt][bkr][bnc + 4] = bv1;
        }
        __syncthreads();
    }

    const float* b1p = b1 + (size_t)e * Hdim + n0 + tn;
#pragma unroll
    for (int i = 0; i < 8; i++) {
        int r = m0 + tm + i;
        if (r < cnt) {
            float* hp = g_h + (size_t)(base + r) * Hdim + n0 + tn;
#pragma unroll
            for (int j = 0; j < 4; j++) {
                float2 v = unpack2(acc[i][j]);
                float2 o;
                o.x = fmaxf(v.x + b1p[j * 2 + 0], 0.f);
                o.y = fmaxf(v.y + b1p[j * 2 + 1], 0.f);
                *(float2*)(hp + j * 2) = o;
            }
        }
    }
}

// ---------------- kernel 5: GEMM2 (R13-proven: K-split x5, atomic out) ----------
__global__ void __launch_bounds__(256, 2)
ffn2_kernel(const float* __restrict__ W2,
            const float* __restrict__ b2) {
    int ty = blockIdx.y;
    if (ty >= g_ntiles) return;
    int e = g_tile_e[ty];
    int cnt = g_cnt[e];
    int m0 = g_tile_m[ty] << 7;
    int base = g_off[e];
    int n0 = blockIdx.x * 128;
    int z = blockIdx.z;
    int cstart = (z < 2) ? z * 39 : 78 + (z - 2) * 38;
    int NC = (z < 2) ? 39 : 38;
    int kbase = cstart * 16;

    const float* Bp = W2 + (size_t)e * Hdim * Ddim;

    __shared__ float As[2][16][132];
    __shared__ float Bs[2][16][128];

    int tid = threadIdx.x;
    int arow = tid >> 1, akc = (tid & 1) * 8;
    int bkr = tid >> 4, bnc = (tid & 15) * 8;
    int tm = (tid >> 4) * 8, tn = (tid & 15) * 8;

    int r_a = m0 + arow;
    if (r_a >= cnt) r_a = cnt - 1;
    const float* ap_base = g_h + (size_t)(base + r_a) * Hdim + kbase + akc;
    const float* bp_base = Bp + (size_t)(kbase + bkr) * Ddim + n0 + bnc;

    unsigned long long acc[8][4];
#pragma unroll
    for (int i = 0; i < 8; i++)
#pragma unroll
        for (int j = 0; j < 4; j++) acc[i][j] = 0ull;

    float4 av0 = *(const float4*)(ap_base);
    float4 av1 = *(const float4*)(ap_base + 4);
    float4 bv0 = *(const float4*)(bp_base);
    float4 bv1 = *(const float4*)(bp_base + 4);

    As[0][akc + 0][arow] = av0.x;  As[0][akc + 1][arow] = av0.y;
    As[0][akc + 2][arow] = av0.z;  As[0][akc + 3][arow] = av0.w;
    As[0][akc + 4][arow] = av1.x;  As[0][akc + 5][arow] = av1.y;
    As[0][akc + 6][arow] = av1.z;  As[0][akc + 7][arow] = av1.w;
    *(float4*)&Bs[0][bkr][bnc]     = bv0;
    *(float4*)&Bs[0][bkr][bnc + 4] = bv1;
    __syncthreads();

    for (int c = 0; c < NC; c++) {
        int cur = c & 1, nxt = cur ^ 1;
        if (c + 1 < NC) {
            int k0 = (c + 1) * 16;
            av0 = *(const float4*)(ap_base + k0);
            av1 = *(const float4*)(ap_base + k0 + 4);
            const float* bp = bp_base + (size_t)k0 * Ddim;
            bv0 = *(const float4*)(bp);
            bv1 = *(const float4*)(bp + 4);
        }
#pragma unroll
        for (int kk = 0; kk < 16; kk++) {
            float4 aA = *(const float4*)&As[cur][kk][tm];
            float4 aB = *(const float4*)&As[cur][kk][tm + 4];
            ulonglong2 bA = *(const ulonglong2*)&Bs[cur][kk][tn];
            ulonglong2 bB = *(const ulonglong2*)&Bs[cur][kk][tn + 4];
            unsigned long long b2v[4] = {bA.x, bA.y, bB.x, bB.y};
            float a[8] = {aA.x, aA.y, aA.z, aA.w, aB.x, aB.y, aB.z, aB.w};
#pragma unroll
            for (int i = 0; i < 8; i++) {
                unsigned long long ai = pack2(a[i]);
#pragma unroll
                for (int j = 0; j < 4; j++) fma2(acc[i][j], ai, b2v[j]);
            }
        }
        if (c + 1 < NC) {
            As[nxt][akc + 0][arow] = av0.x;  As[nxt][akc + 1][arow] = av0.y;
            As[nxt][akc + 2][arow] = av0.z;  As[nxt][akc + 3][arow] = av0.w;
            As[nxt][akc + 4][arow] = av1.x;  As[nxt][akc + 5][arow] = av1.y;
            As[nxt][akc + 6][arow] = av1.z;  As[nxt][akc + 7][arow] = av1.w;
            *(float4*)&Bs[nxt][bkr][bnc]     = bv0;
            *(float4*)&Bs[nxt][bkr][bnc + 4] = bv1;
        }
        __syncthreads();
    }

    const float* b2p = b2 + (size_t)e * Ddim + n0 + tn;
#pragma unroll
    for (int i = 0; i < 8; i++) {
        int r = m0 + tm + i;
        if (r < cnt) {
            float g = g_gate[base + r];
            float* yp = g_yd + (size_t)(base + r) * Ddim + n0 + tn;
#pragma unroll
            for (int j = 0; j < 4; j++) {
                float2 v = unpack2(acc[i][j]);
                float p0 = g * v.x;
                float p1 = g * v.y;
                if (z == 0) {
                    p0 += g * b2p[j * 2 + 0];
                    p1 += g * b2p[j * 2 + 1];
                }
                atomicAdd(yp + j * 2 + 0, p0);
                atomicAdd(yp + j * 2 + 1, p1);
            }
        }
    }
}

// ---------------- kernel 6: combine ---------------------------------------------
__global__ void combine_kernel(float* __restrict__ out) {
    int idx = blockIdx.x * blockDim.x + threadIdx.x;
    int total = NTOK * Ddim / 4;
    if (idx >= total) return;
    int t = idx / (Ddim / 4);
    int d4 = idx % (Ddim / 4);
    int p0 = g_pos[t * 2 + 0];
    int p1 = g_pos[t * 2 + 1];
    float4 a = *(const float4*)(g_yd + (size_t)p0 * Ddim + d4 * 4);
    float4 b = *(const float4*)(g_yd + (size_t)p1 * Ddim + d4 * 4);
    float4 o;
    o.x = a.x + b.x; o.y = a.y + b.y; o.z = a.z + b.z; o.w = a.w + b.w;
    *(float4*)(out + (size_t)t * Ddim + d4 * 4) = o;
}

// ---------------- launch ---------------------------------------------------------
extern "C" void kernel_launch(void* const* d_in, const int* in_sizes, int n_in,
                              void* d_out, int out_size) {
    const float* x       = (const float*)d_in[0];
    const float* noise   = (const float*)d_in[1];
    const float* w_route = (const float*)d_in[2];
    const float* b_route = (const float*)d_in[3];
    const float* w_noise = (const float*)d_in[4];
    const float* b_noise = (const float*)d_in[5];
    const float* W1      = (const float*)d_in[6];
    const float* b1      = (const float*)d_in[7];
    const float* W2      = (const float*)d_in[8];
    const float* b2      = (const float*)d_in[9];
    float* out = (float*)d_out;

    zero_kernel<<<1, 32>>>();
    router_kernel<<<NTOK / 8, 256>>>(x, noise, w_route, b_route, w_noise, b_noise);
    scan_kernel<<<1, 1>>>();
    fill_kernel<<<(NDISP + 255) / 256, 256>>>();
    yzero_kernel<<<(NDISP * (Ddim / 4) + 255) / 256, 256>>>();
    ffn1_kernel<<<dim3(Hdim / 128, MAXTILES), 256>>>(x, W1, b1);
    ffn2_kernel<<<dim3(Ddim / 128, MAXTILES, KSPLIT), 256>>>(W2, b2);
    combine_kernel<<<(NTOK * Ddim / 4 + 255) / 256, 256>>>(out);
}